// round 16
// baseline (speedup 1.0000x reference)
#include <cuda_runtime.h>
#include <math.h>
#include <stdint.h>

#define BB 4
#define SEQ 1024
#define HIDDEN 4096
#define NH 32
#define NKV 8
#define DH 128
#define RL 16
#define QDIM (NH*DH)
#define KVDIM (NKV*DH)
#define NTILE (SEQ/64)

__device__ float g_q[(size_t)BB*SEQ*QDIM];
__device__ float g_k[(size_t)BB*SEQ*KVDIM];
__device__ float g_v[(size_t)BB*SEQ*KVDIM];
__device__ float g_attn[(size_t)BB*SEQ*QDIM];
__device__ float g_t[(size_t)3*BB*SEQ*RL];
__device__ float g_cos[SEQ*(DH/2)];
__device__ float g_sin[SEQ*(DH/2)];
// bf16 hi/lo packed operands: [0, half) = hi pairs, [half, 2*half) = lo pairs
__device__ uint32_t g_xt[(size_t)BB*SEQ*HIDDEN];
__device__ uint32_t g_wqt[(size_t)QDIM*HIDDEN];
__device__ uint32_t g_wkt[(size_t)KVDIM*HIDDEN];
__device__ uint32_t g_wvt[(size_t)KVDIM*HIDDEN];
__device__ uint32_t g_wot[(size_t)HIDDEN*QDIM];
__device__ uint32_t g_at[(size_t)BB*SEQ*QDIM];

#define KTILE_W (2*64*68)
#define VTILE_W (2*128*36)
__device__ uint32_t g_kp[(size_t)BB*NKV*NTILE*KTILE_W];
__device__ uint32_t g_vp[(size_t)BB*NKV*NTILE*VTILE_W];

__device__ __forceinline__ uint32_t pbf2(float lo, float hi) {
    uint32_t r;
    asm("cvt.rn.bf16x2.f32 %0, %1, %2;" : "=r"(r) : "f"(hi), "f"(lo));
    return r;
}
__device__ __forceinline__ float xlo(uint32_t w) { return __uint_as_float(w << 16); }
__device__ __forceinline__ float xhi(uint32_t w) { return __uint_as_float(w & 0xffff0000u); }

#define MMA_BF16(c0,c1,c2,c3,a0,a1,a2,a3,b0,b1)                              \
    asm volatile("mma.sync.aligned.m16n8k16.row.col.f32.bf16.bf16.f32 "      \
        "{%0,%1,%2,%3}, {%4,%5,%6,%7}, {%8,%9}, {%0,%1,%2,%3};"              \
        : "+f"(c0),"+f"(c1),"+f"(c2),"+f"(c3)                                \
        : "r"(a0),"r"(a1),"r"(a2),"r"(a3),"r"(b0),"r"(b1))

__device__ __forceinline__ void cp_async16(void* smem_dst, const void* gsrc) {
    uint32_t d = (uint32_t)__cvta_generic_to_shared(smem_dst);
    asm volatile("cp.async.cg.shared.global [%0], [%1], 16;" :: "r"(d), "l"(gsrc));
}
__device__ __forceinline__ void cp_commit() {
    asm volatile("cp.async.commit_group;");
}

// split fp32 stream into bf16 hi/lo pair words
__global__ void cvt_bf16_kernel(const float4* __restrict__ in,
                                uint2* __restrict__ hi, uint2* __restrict__ lo,
                                int n4) {
    int i = blockIdx.x * blockDim.x + threadIdx.x;
    if (i >= n4) return;
    float4 v = in[i];
    uint32_t h0 = pbf2(v.x, v.y);
    uint32_t h1 = pbf2(v.z, v.w);
    uint32_t l0 = pbf2(v.x - xlo(h0), v.y - xhi(h0));
    uint32_t l1 = pbf2(v.z - xlo(h1), v.w - xhi(h1));
    hi[i] = make_uint2(h0, h1);
    lo[i] = make_uint2(l0, l1);
}

__global__ void rope_tables_kernel() {
    int idx = blockIdx.x * blockDim.x + threadIdx.x;
    if (idx >= SEQ * (DH/2)) return;
    int s = idx / (DH/2);
    int j = idx % (DH/2);
    float e = -(float)j * (13.287712379549449f / 64.0f);
    float inv = exp2f(e);
    float ang = (float)s * inv;
    g_cos[idx] = cosf(ang);
    g_sin[idx] = sinf(ang);
}

__global__ __launch_bounds__(256) void lora_qkv_kernel(
    const float* __restrict__ x, const float* __restrict__ Aq,
    const float* __restrict__ Ak, const float* __restrict__ Av,
    float* __restrict__ t)
{
    const int g = threadIdx.x >> 6;
    const int j = threadIdx.x & 63;
    const int row = blockIdx.x * 4 + g;
    const int b = row / SEQ;
    const float* xr = x + (size_t)row * HIDDEN;
    const float* Ab0 = Aq + (size_t)b * RL * HIDDEN;
    const float* Ab1 = Ak + (size_t)b * RL * HIDDEN;
    const float* Ab2 = Av + (size_t)b * RL * HIDDEN;

    float acc[3][RL];
#pragma unroll
    for (int p = 0; p < 3; p++)
#pragma unroll
        for (int r = 0; r < RL; r++) acc[p][r] = 0.f;

    for (int k = j * 4; k < HIDDEN; k += 256) {
        float4 xv = *(const float4*)(xr + k);
#pragma unroll
        for (int r = 0; r < RL; r++) {
            float4 a0 = *(const float4*)(Ab0 + (size_t)r * HIDDEN + k);
            float4 a1 = *(const float4*)(Ab1 + (size_t)r * HIDDEN + k);
            float4 a2 = *(const float4*)(Ab2 + (size_t)r * HIDDEN + k);
            acc[0][r] += fmaf(xv.x, a0.x, fmaf(xv.y, a0.y, fmaf(xv.z, a0.z, xv.w * a0.w)));
            acc[1][r] += fmaf(xv.x, a1.x, fmaf(xv.y, a1.y, fmaf(xv.z, a1.z, xv.w * a1.w)));
            acc[2][r] += fmaf(xv.x, a2.x, fmaf(xv.y, a2.y, fmaf(xv.z, a2.z, xv.w * a2.w)));
        }
    }

    __shared__ float red[4][64][17];
#pragma unroll
    for (int p = 0; p < 3; p++) {
        __syncthreads();
#pragma unroll
        for (int r = 0; r < RL; r++) red[g][j][r] = acc[p][r];
        __syncthreads();
        if (j < RL) {
            float s = 0.f;
#pragma unroll 8
            for (int jj = 0; jj < 64; jj++) s += red[g][jj][j];
            t[(size_t)p * BB * SEQ * RL + (size_t)row * RL + j] = s;
        }
    }
}

__global__ __launch_bounds__(256) void lora_a_kernel(
    const float* __restrict__ x, const float* __restrict__ A,
    float* __restrict__ t, int K)
{
    const int g = threadIdx.x >> 6;
    const int j = threadIdx.x & 63;
    const int row = blockIdx.x * 4 + g;
    const int b = row / SEQ;
    const float* xr = x + (size_t)row * K;
    const float* Ab = A + (size_t)b * RL * K;

    float acc[RL];
#pragma unroll
    for (int r = 0; r < RL; r++) acc[r] = 0.f;

    for (int k = j * 4; k < K; k += 256) {
        float4 xv = *(const float4*)(xr + k);
#pragma unroll
        for (int r = 0; r < RL; r++) {
            float4 av = *(const float4*)(Ab + (size_t)r * K + k);
            acc[r] += fmaf(xv.x, av.x, fmaf(xv.y, av.y, fmaf(xv.z, av.z, xv.w * av.w)));
        }
    }

    __shared__ float red[4][64][17];
#pragma unroll
    for (int r = 0; r < RL; r++) red[g][j][r] = acc[r];
    __syncthreads();
    if (j < RL) {
        float s = 0.f;
#pragma unroll 8
        for (int jj = 0; jj < 64; jj++) s += red[g][jj][j];
        t[(size_t)row * RL + j] = s;
    }
}

// ---------------- bf16-split MMA GEMM v9: 64x64 warp tile, 128 threads -------
// smem per stage: Ahi[128][20] Alo Bhi Blo (words); 2 stages
#define BM 128
#define BN 128
#define BK 32
#define KPB 20
#define STG9 (4*128*KPB)          // words per stage = 10240
#define GEMM_SMEM (2*STG9*4)      // 81920 B

__global__ __launch_bounds__(128, 2) void gemm_lora_v9(
    const uint32_t* __restrict__ Xh, const uint32_t* __restrict__ Xl,
    const uint32_t* __restrict__ Wh, const uint32_t* __restrict__ Wl,
    const float* __restrict__ T, const float* __restrict__ BL,
    float* __restrict__ C, int N, int K)
{
    extern __shared__ uint32_t sm3[];

    const int b  = blockIdx.z;
    const int n0 = blockIdx.x * BN;
    const int m0 = blockIdx.y * BM;
    const int KP = K >> 1;            // pair words per row
    const uint32_t* Xhb = Xh + (size_t)b * SEQ * KP;
    const uint32_t* Xlb = Xl + (size_t)b * SEQ * KP;
    const float* Tb = T + (size_t)b * SEQ * RL;
    const float* Ub = BL + (size_t)b * N * RL;
    float* Cb = C + (size_t)b * SEQ * N;

    const int tid  = threadIdx.x;
    const int warp = tid >> 5;
    const int lane = tid & 31;
    const int wm = (warp & 1) * 64;
    const int wn = (warp >> 1) * 64;
    const int gid = lane >> 2;
    const int tig = lane & 3;

    float acc[4][8][4];
#pragma unroll
    for (int mf = 0; mf < 4; mf++)
#pragma unroll
        for (int nf = 0; nf < 8; nf++)
#pragma unroll
            for (int c = 0; c < 4; c++) acc[mf][nf][c] = 0.f;

    const int KT = K / BK;

    // prologue: stage 0 (pair offset 0)
    {
        uint32_t* Ahi = sm3;
        uint32_t* Alo = sm3 + 128*KPB;
        uint32_t* Bhi = sm3 + 2*128*KPB;
        uint32_t* Blo = sm3 + 3*128*KPB;
#pragma unroll
        for (int i = 0; i < 4; i++) {
            int idx = tid + i * 128;
            int row = idx >> 2, seg = idx & 3;
            cp_async16(&Ahi[row*KPB + seg*4], Xhb + (size_t)(m0 + row) * KP + seg*4);
            cp_async16(&Alo[row*KPB + seg*4], Xlb + (size_t)(m0 + row) * KP + seg*4);
            cp_async16(&Bhi[row*KPB + seg*4], Wh + (size_t)(n0 + row) * KP + seg*4);
            cp_async16(&Blo[row*KPB + seg*4], Wl + (size_t)(n0 + row) * KP + seg*4);
        }
        cp_commit();
    }

    for (int kt = 0; kt < KT; kt++) {
        const int s = kt & 1;
        if (kt + 1 < KT) {
            const int sn = s ^ 1;
            const int k0p = (kt + 1) * (BK/2);
            uint32_t* Ahi = sm3 + sn*STG9;
            uint32_t* Alo = Ahi + 128*KPB;
            uint32_t* Bhi = Ahi + 2*128*KPB;
            uint32_t* Blo = Ahi + 3*128*KPB;
#pragma unroll
            for (int i = 0; i < 4; i++) {
                int idx = tid + i * 128;
                int row = idx >> 2, seg = idx & 3;
                cp_async16(&Ahi[row*KPB + seg*4], Xhb + (size_t)(m0 + row) * KP + k0p + seg*4);
                cp_async16(&Alo[row*KPB + seg*4], Xlb + (size_t)(m0 + row) * KP + k0p + seg*4);
                cp_async16(&Bhi[row*KPB + seg*4], Wh + (size_t)(n0 + row) * KP + k0p + seg*4);
                cp_async16(&Blo[row*KPB + seg*4], Wl + (size_t)(n0 + row) * KP + k0p + seg*4);
            }
            cp_commit();
            asm volatile("cp.async.wait_group 1;");
        } else {
            asm volatile("cp.async.wait_group 0;");
        }
        __syncthreads();

        const uint32_t* Ahi = sm3 + s*STG9;
        const uint32_t* Alo = Ahi + 128*KPB;
        const uint32_t* Bhi = Ahi + 2*128*KPB;
        const uint32_t* Blo = Ahi + 3*128*KPB;
#pragma unroll
        for (int ks = 0; ks < 2; ks++) {
            const int kb = ks * 8;
            uint32_t ah[4][4], al[4][4];
#pragma unroll
            for (int mf = 0; mf < 4; mf++) {
                int r0 = (wm + mf*16 + gid) * KPB + kb;
                int r1 = (wm + mf*16 + 8 + gid) * KPB + kb;
                ah[mf][0] = Ahi[r0 + tig];     ah[mf][1] = Ahi[r1 + tig];
                ah[mf][2] = Ahi[r0 + tig + 4]; ah[mf][3] = Ahi[r1 + tig + 4];
                al[mf][0] = Alo[r0 + tig];     al[mf][1] = Alo[r1 + tig];
                al[mf][2] = Alo[r0 + tig + 4]; al[mf][3] = Alo[r1 + tig + 4];
            }
#pragma unroll
            for (int nf = 0; nf < 8; nf++) {
                int nr = (wn + nf*8 + gid) * KPB + kb;
                uint32_t bh0 = Bhi[nr + tig], bh1 = Bhi[nr + tig + 4];
                uint32_t bl0 = Blo[nr + tig], bl1 = Blo[nr + tig + 4];
#pragma unroll
                for (int mf = 0; mf < 4; mf++) {
                    MMA_BF16(acc[mf][nf][0], acc[mf][nf][1], acc[mf][nf][2], acc[mf][nf][3],
                             ah[mf][0], ah[mf][1], ah[mf][2], ah[mf][3], bh0, bh1);
                    MMA_BF16(acc[mf][nf][0], acc[mf][nf][1], acc[mf][nf][2], acc[mf][nf][3],
                             al[mf][0], al[mf][1], al[mf][2], al[mf][3], bh0, bh1);
                    MMA_BF16(acc[mf][nf][0], acc[mf][nf][1], acc[mf][nf][2], acc[mf][nf][3],
                             ah[mf][0], ah[mf][1], ah[mf][2], ah[mf][3], bl0, bl1);
                }
            }
        }
        __syncthreads();
    }

    float* Ts = (float*)sm3;
    float* Us = (float*)(sm3 + 128 * RL);
#pragma unroll
    for (int i = 0; i < 4; i++) {
        int f4 = tid + i * 128;
        int row = f4 >> 2;
        int c4 = (f4 & 3) * 4;
        *(float4*)&Ts[row * RL + c4] = *(const float4*)&Tb[(size_t)(m0 + row) * RL + c4];
        *(float4*)&Us[row * RL + c4] = *(const float4*)&Ub[(size_t)(n0 + row) * RL + c4];
    }
    __syncthreads();

#pragma unroll
    for (int mf = 0; mf < 4; mf++) {
#pragma unroll
        for (int rr = 0; rr < 2; rr++) {
            int m_local = wm + mf * 16 + rr * 8 + gid;
            float tv[RL];
#pragma unroll
            for (int r = 0; r < RL; r++) tv[r] = Ts[m_local * RL + r];
            size_t crow = (size_t)(m0 + m_local) * N + n0;
#pragma unroll
            for (int nf = 0; nf < 8; nf++) {
                int n_local = wn + nf * 8 + 2 * tig;
                float s0 = acc[mf][nf][rr * 2 + 0];
                float s1 = acc[mf][nf][rr * 2 + 1];
#pragma unroll
                for (int r = 0; r < RL; r++) {
                    s0 = fmaf(tv[r], Us[n_local * RL + r], s0);
                    s1 = fmaf(tv[r], Us[(n_local + 1) * RL + r], s1);
                }
                *(float2*)&Cb[crow + n_local] = make_float2(s0, s1);
            }
        }
    }
}

__global__ __launch_bounds__(256) void kprep_kernel() {
    const int jt = blockIdx.x, hk = blockIdx.y, b = blockIdx.z;
    const int tid = threadIdx.x;
    const int r = tid >> 2;
    const int pb = (tid & 3) * 16;
    const int s = jt * 64 + r;
    const float* src = g_k + (((size_t)(b * SEQ + s)) * NKV + hk) * DH;
    size_t tile = ((size_t)(b * NKV + hk) * NTILE + jt);
    uint32_t* dhi = g_kp + tile * KTILE_W + (size_t)r * 68;
    uint32_t* dlo = dhi + 64 * 68;

#pragma unroll
    for (int u4 = 0; u4 < 4; u4++) {
        float4 xa = *(const float4*)(src + pb + u4 * 4);
        float4 xb = *(const float4*)(src + pb + 64 + u4 * 4);
        float4 cc = *(const float4*)(g_cos + s * 64 + pb + u4 * 4);
        float4 ss = *(const float4*)(g_sin + s * 64 + pb + u4 * 4);
        float x1[4] = {xa.x, xa.y, xa.z, xa.w};
        float x2[4] = {xb.x, xb.y, xb.z, xb.w};
        float cv[4] = {cc.x, cc.y, cc.z, cc.w};
        float sv[4] = {ss.x, ss.y, ss.z, ss.w};
        float y1[4], y2[4];
#pragma unroll
        for (int e = 0; e < 4; e++) {
            y1[e] = fmaf(x1[e], cv[e], -x2[e] * sv[e]);
            y2[e] = fmaf(x2[e], cv[e],  x1[e] * sv[e]);
        }
        int p1 = (pb + u4 * 4) >> 1;
#pragma unroll
        for (int pp = 0; pp < 2; pp++) {
            float a0 = y1[pp*2], a1 = y1[pp*2+1];
            uint32_t hw = pbf2(a0, a1);
            uint32_t lw = pbf2(a0 - xlo(hw), a1 - xhi(hw));
            dhi[p1 + pp] = hw;
            dlo[p1 + pp] = lw;
            float b0 = y2[pp*2], b1 = y2[pp*2+1];
            uint32_t hw2 = pbf2(b0, b1);
            uint32_t lw2 = pbf2(b0 - xlo(hw2), b1 - xhi(hw2));
            dhi[p1 + 32 + pp] = hw2;
            dlo[p1 + 32 + pp] = lw2;
        }
    }
}

__global__ __launch_bounds__(256) void vprep_kernel() {
    const int jt = blockIdx.x, hk = blockIdx.y, b = blockIdx.z;
    const int tid = threadIdx.x;
    const int jp = tid & 31;
    const int dblk = tid >> 5;
    const float* s0 = g_v + (((size_t)(b * SEQ + jt * 64 + 2*jp))   * NKV + hk) * DH + dblk * 16;
    const float* s1 = g_v + (((size_t)(b * SEQ + jt * 64 + 2*jp+1)) * NKV + hk) * DH + dblk * 16;
    size_t tile = ((size_t)(b * NKV + hk) * NTILE + jt);
    uint32_t* dhi = g_vp + tile * VTILE_W;
    uint32_t* dlo = dhi + 128 * 36;

#pragma unroll
    for (int u = 0; u < 4; u++) {
        float4 va = *(const float4*)(s0 + u * 4);
        float4 vb = *(const float4*)(s1 + u * 4);
        float a[4] = {va.x, va.y, va.z, va.w};
        float bb[4] = {vb.x, vb.y, vb.z, vb.w};
#pragma unroll
        for (int e = 0; e < 4; e++) {
            int d = dblk * 16 + u * 4 + e;
            uint32_t hw = pbf2(a[e], bb[e]);
            uint32_t lw = pbf2(a[e] - xlo(hw), bb[e] - xhi(hw));
            dhi[d * 36 + jp] = hw;
            dlo[d * 36 + jp] = lw;
        }
    }
}

#define ATTN_SMEM 214784
#define QPS 68
#define VPS 36
#define PSS 68
#define STG_W 17920

__global__ __launch_bounds__(256, 1) void attn_mma_kernel() {
    extern __shared__ char smraw[];
    uint32_t* smw = (uint32_t*)smraw;
    uint32_t* Qhi = smw;
    uint32_t* Qlo = smw + 4352;
    float*    Psf = (float*)(smw + 44544);
    uint32_t* Phi = smw + 48896;
    uint32_t* Plo = smw + 51200;
    float* mrow = (float*)(smw + 53504);
    float* lrow = mrow + 64;
    float* arow = mrow + 128;

    const int qt = (NTILE - 1) - blockIdx.x;
    const int h  = blockIdx.y;
    const int b  = blockIdx.z;
    const int hk = h >> 2;
    const int tid  = threadIdx.x;
    const int warp = tid >> 5;
    const int lane = tid & 31;
    const int gid = lane >> 2;
    const int tig = lane & 3;
    const int wm  = (warp & 3) * 16;
    const int wn  = (warp >> 2) * 32;
    const int wdn = (warp >> 2) * 64;

    const size_t tbase = (size_t)(b * NKV + hk) * NTILE;
    const float scale = 0.08838834764831845f;

    {
        const char* gk = (const char*)(g_kp + (tbase + 0) * KTILE_W);
        char* sk = smraw + 8704 * 4;
#pragma unroll
        for (int i = 0; i < 9; i++) {
            int idx = tid + i * 256;
            if (idx < 2176) cp_async16(sk + idx * 16, gk + idx * 16);
        }
        const char* gv = (const char*)(g_vp + (tbase + 0) * VTILE_W);
        char* sv = sk + 34816;
#pragma unroll
        for (int i = 0; i < 9; i++) {
            int idx = tid + i * 256;
            cp_async16(sv + idx * 16, gv + idx * 16);
        }
        cp_commit();
    }

    {
        int r = tid >> 2;
        int q4 = tid & 3;
        int sg = qt * 64 + r;
        const float* src = g_q + (((size_t)(b * SEQ + sg)) * NH + h) * DH;
        const float* cb = g_cos + sg * 64 + q4 * 16;
        const float* sb = g_sin + sg * 64 + q4 * 16;
        int pA = q4 * 8;
#pragma unroll
        for (int u = 0; u < 4; u++) {
            float4 xa = *(const float4*)(src + q4 * 16 + u * 4);
            float4 xb = *(const float4*)(src + q4 * 16 + 64 + u * 4);
            float4 cc = *(const float4*)(cb + u * 4);
            float4 ss = *(const float4*)(sb + u * 4);
            float x1[4] = {xa.x, xa.y, xa.z, xa.w};
            float x2[4] = {xb.x, xb.y, xb.z, xb.w};
            float cv[4] = {cc.x, cc.y, cc.z, cc.w};
            float sv[4] = {ss.x, ss.y, ss.z, ss.w};
            float y1[4], y2[4];
#pragma unroll
            for (int e = 0; e < 4; e++) {
                y1[e] = fmaf(x1[e], cv[e], -x2[e] * sv[e]) * scale;
                y2[e] = fmaf(x2[e], cv[e],  x1[e] * sv[e]) * scale;
            }
            int cbase = r * QPS + pA + u * 2;
#pragma unroll
            for (int pp = 0; pp < 2; pp++) {
                uint32_t hw = pbf2(y1[pp*2], y1[pp*2+1]);
                uint32_t lw = pbf2(y1[pp*2] - xlo(hw), y1[pp*2+1] - xhi(hw));
                Qhi[cbase + pp] = hw;
                Qlo[cbase + pp] = lw;
                uint32_t hw2 = pbf2(y2[pp*2], y2[pp*2+1]);
                uint32_t lw2 = pbf2(y2[pp*2] - xlo(hw2), y2[pp*2+1] - xhi(hw2));
                Qhi[cbase + 32 + pp] = hw2;
                Qlo[cbase + 32 + pp] = lw2;
            }
        }
    }
    if (tid < 64) { mrow[tid] = -1e30f; lrow[tid] = 0.f; }
    __syncthreads();

    uint32_t ah[8][4];
#pragma unroll
    for (int ks = 0; ks < 8; ks++) {
        int kb = ks * 8;
        ah[ks][0] = Qhi[(wm + gid)     * QPS + kb + tig];
        ah[ks][1] = Qhi[(wm + gid + 8) * QPS + kb + tig];
        ah[ks][2] = Qhi[(wm + gid)     * QPS + kb + tig + 4];
        ah[ks][3] = Qhi[(wm + gid + 8) * QPS + kb + tig + 4];
    }

    float o[8][4];
#pragma unroll
    for (int nf = 0; nf < 8; nf++)
#pragma unroll
        for (int c = 0; c < 4; c++) o[nf][c] = 0.f;

    for (int jt = 0; jt <= qt; jt++) {
        const int st = jt & 1;
        uint32_t* Khi = smw + 8704 + st * STG_W;
        uint32_t* Klo = Khi + 4352;
        uint32_t* Vhi = Khi + 8704;
        uint32_t* Vlo = Khi + 13312;

        asm volatile("cp.async.wait_group 0;");
        __syncthreads();

        if (jt < qt) {
            const int sn = st ^ 1;
            const char* gk = (const char*)(g_kp + (tbase + jt + 1) * KTILE_W);
            char* sk = smraw + (8704 + sn * STG_W) * 4;
#pragma unroll
            for (int i = 0; i < 9; i++) {
                int idx = tid + i * 256;
                if (idx < 2176) cp_async16(sk + idx * 16, gk + idx * 16);
            }
            const char* gv = (const char*)(g_vp + (tbase + jt + 1) * VTILE_W);
            char* sv = sk + 34816;
#pragma unroll
            for (int i = 0; i < 9; i++) {
                int idx = tid + i * 256;
                cp_async16(sv + idx * 16, gv + idx * 16);
            }
            cp_commit();
        }

        float s[4][4];
#pragma unroll
        for (int nf = 0; nf < 4; nf++)
#pragma unroll
            for (int c = 0; c < 4; c++) s[nf][c] = 0.f;

#pragma unroll
        for (int ks = 0; ks < 8; ks++) {
            int kb = ks * 8;
            uint32_t ql0 = Qlo[(wm + gid)     * QPS + kb + tig];
            uint32_t ql1 = Qlo[(wm + gid + 8) * QPS + kb + tig];
            uint32_t ql2 = Qlo[(wm + gid)     * QPS + kb + tig + 4];
            uint32_t ql3 = Qlo[(wm + gid + 8) * QPS + kb + tig + 4];
#pragma unroll
            for (int nf = 0; nf < 4; nf++) {
                int nr = (wn + nf * 8 + gid) * QPS + kb;
                uint32_t bh0 = Khi[nr + tig];
                uint32_t bh1 = Khi[nr + tig + 4];
                uint32_t bl0 = Klo[nr + tig];
                uint32_t bl1 = Klo[nr + tig + 4];
                MMA_BF16(s[nf][0], s[nf][1], s[nf][2], s[nf][3],
                         ah[ks][0], ah[ks][1], ah[ks][2], ah[ks][3], bh0, bh1);
                MMA_BF16(s[nf][0], s[nf][1], s[nf][2], s[nf][3],
                         ql0, ql1, ql2, ql3, bh0, bh1);
                MMA_BF16(s[nf][0], s[nf][1], s[nf][2], s[nf][3],
                         ah[ks][0], ah[ks][1], ah[ks][2], ah[ks][3], bl0, bl1);
            }
        }

        {
            int row0 = wm + gid, row1 = row0 + 8;
            int rg0 = qt * 64 + row0, rg1 = qt * 64 + row1;
#pragma unroll
            for (int nf = 0; nf < 4; nf++) {
                int cc = wn + nf * 8 + 2 * tig;
                int cg = jt * 64 + cc;
                float2 w0, w1;
                w0.x = (cg     <= rg0) ? s[nf][0] : -1e30f;
                w0.y = (cg + 1 <= rg0) ? s[nf][1] : -1e30f;
                w1.x = (cg     <= rg1) ? s[nf][2] : -1e30f;
                w1.y = (cg + 1 <= rg1) ? s[nf][3] : -1e30f;
                *(float2*)(Psf + row0 * PSS + cc) = w0;
                *(float2*)(Psf + row1 * PSS + cc) = w1;
            }
        }
        __syncthreads();

        {
            int sr = tid >> 2;
            int t4 = tid & 3;
            float* prow = Psf + sr * PSS + t4 * 16;
            float pv[16];
            float mx = -1e30f;
#pragma unroll
            for (int i = 0; i < 16; i++) { pv[i] = prow[i]; mx = fmaxf(mx, pv[i]); }
            mx = fmaxf(mx, __shfl_xor_sync(0xffffffffu, mx, 1));
            mx = fmaxf(mx, __shfl_xor_sync(0xffffffffu, mx, 2));
            float mo = mrow[sr];
            mx = fmaxf(mx, mo);
            float sum = 0.f;
            uint32_t* ph = Phi + sr * VPS + t4 * 8;
            uint32_t* pl = Plo + sr * VPS + t4 * 8;
#pragma unroll
            for (int i = 0; i < 8; i++) {
                float e0 = __expf(pv[2*i]   - mx);
                float e1 = __expf(pv[2*i+1] - mx);
                sum += e0 + e1;
                uint32_t hw = pbf2(e0, e1);
                uint32_t lw = pbf2(e0 - xlo(hw), e1 - xhi(hw));
                ph[i] = hw;
                pl[i] = lw;
            }
            sum += __shfl_xor_sync(0xffffffffu, sum, 1);
            sum += __shfl_xor_sync(0xffffffffu, sum, 2);
            if (t4 == 0) {
                float alp = __expf(mo - mx);
                lrow[sr] = lrow[sr] * alp + sum;
                mrow[sr] = mx;
                arow[sr] = alp;
            }
        }
        __syncthreads();

        {
            float a0 = arow[wm + gid];
            float a1 = arow[wm + gid + 8];
#pragma unroll
            for (int nf = 0; nf < 8; nf++) {
                o[nf][0] *= a0; o[nf][1] *= a0;
                o[nf][2] *= a1; o[nf][3] *= a1;
            }
        }

#pragma unroll
        for (int ks = 0; ks < 4; ks++) {
            int kb = ks * 8;
            uint32_t ph0 = Phi[(wm + gid)     * VPS + kb + tig];
            uint32_t ph1 = Phi[(wm + gid + 8) * VPS + kb + tig];
            uint32_t ph2 = Phi[(wm + gid)     * VPS + kb + tig + 4];
            uint32_t ph3 = Phi[(wm + gid + 8) * VPS + kb + tig + 4];
            uint32_t pl0 = Plo[(wm + gid)     * VPS + kb + tig];
            uint32_t pl1 = Plo[(wm + gid + 8) * VPS + kb + tig];
            uint32_t pl2 = Plo[(wm + gid)     * VPS + kb + tig + 4];
            uint32_t pl3 = Plo[(wm + gid + 8) * VPS + kb + tig + 4];
#pragma unroll
            for (int nf = 0; nf < 8; nf++) {
                int dv = (wdn + nf * 8 + gid) * VPS + kb;
                uint32_t vh0 = Vhi[dv + tig], vh1 = Vhi[dv + tig + 4];
                uint32_t vl0 = Vlo[dv + tig], vl1 = Vlo[dv + tig + 4];
                MMA_BF16(o[nf][0], o[nf][1], o[nf][2], o[nf][3],
                         ph0, ph1, ph2, ph3, vh0, vh1);
                MMA_BF16(o[nf][0], o[nf][1], o[nf][2], o[nf][3],
                         pl0, pl1, pl2, pl3, vh0, vh1);
                MMA_BF16(o[nf][0], o[nf][1], o[nf][2], o[nf][3],
                         ph0, ph1, ph2, ph3, vl0, vl1);
            }
        }
    }

    {
        float li0 = 1.f / lrow[wm + gid];
        float li1 = 1.f / lrow[wm + gid + 8];
        size_t base0 = (((size_t)(b * SEQ + qt * 64 + wm + gid))     * NH + h) * DH;
        size_t base1 = (((size_t)(b * SEQ + qt * 64 + wm + gid + 8)) * NH + h) * DH;
#pragma unroll
        for (int nf = 0; nf < 8; nf++) {
            int cc = wdn + nf * 8 + 2 * tig;
            *(float2*)(g_attn + base0 + cc) = make_float2(o[nf][0] * li0, o[nf][1] * li0);
            *(float2*)(g_attn + base1 + cc) = make_float2(o[nf][2] * li1, o[nf][3] * li1);
        }
    }
}

extern "C" void kernel_launch(void* const* d_in, const int* in_sizes, int n_in,
                              void* d_out, int out_size) {
    const float* x  = (const float*)d_in[0];
    const float* Wq = (const float*)d_in[1];
    const float* Wk = (const float*)d_in[2];
    const float* Wv = (const float*)d_in[3];
    const float* Wo = (const float*)d_in[4];
    const float* Aq = (const float*)d_in[5];
    const float* Bq = (const float*)d_in[6];
    const float* Ak = (const float*)d_in[7];
    const float* Bk = (const float*)d_in[8];
    const float* Av = (const float*)d_in[9];
    const float* Bv = (const float*)d_in[10];
    const float* Ao = (const float*)d_in[11];
    const float* Bo = (const float*)d_in[12];
    float* out = (float*)d_out;

    float *q_ptr, *k_ptr, *v_ptr, *attn_ptr, *t_ptr;
    uint32_t *xt_ptr, *wqt_ptr, *wkt_ptr, *wvt_ptr, *wot_ptr, *at_ptr;
    cudaGetSymbolAddress((void**)&q_ptr, g_q);
    cudaGetSymbolAddress((void**)&k_ptr, g_k);
    cudaGetSymbolAddress((void**)&v_ptr, g_v);
    cudaGetSymbolAddress((void**)&attn_ptr, g_attn);
    cudaGetSymbolAddress((void**)&t_ptr, g_t);
    cudaGetSymbolAddress((void**)&xt_ptr, g_xt);
    cudaGetSymbolAddress((void**)&wqt_ptr, g_wqt);
    cudaGetSymbolAddress((void**)&wkt_ptr, g_wkt);
    cudaGetSymbolAddress((void**)&wvt_ptr, g_wvt);
    cudaGetSymbolAddress((void**)&wot_ptr, g_wot);
    cudaGetSymbolAddress((void**)&at_ptr, g_at);

    cudaFuncSetAttribute(attn_mma_kernel,
                         cudaFuncAttributeMaxDynamicSharedMemorySize, ATTN_SMEM);
    cudaFuncSetAttribute(gemm_lora_v9,
                         cudaFuncAttributeMaxDynamicSharedMemorySize, GEMM_SMEM);

    rope_tables_kernel<<<(SEQ*(DH/2) + 255)/256, 256>>>();

    // bf16 hi/lo pre-split of GEMM operands (hi in first half, lo in second)
    {
        int n4;
        n4 = BB*SEQ*HIDDEN/4;
        cvt_bf16_kernel<<<(n4 + 255)/256, 256>>>((const float4*)x,
            (uint2*)xt_ptr, (uint2*)xt_ptr + n4, n4);
        n4 = QDIM*HIDDEN/4;
        cvt_bf16_kernel<<<(n4 + 255)/256, 256>>>((const float4*)Wq,
            (uint2*)wqt_ptr, (uint2*)wqt_ptr + n4, n4);
        n4 = KVDIM*HIDDEN/4;
        cvt_bf16_kernel<<<(n4 + 255)/256, 256>>>((const float4*)Wk,
            (uint2*)wkt_ptr, (uint2*)wkt_ptr + n4, n4);
        cvt_bf16_kernel<<<(n4 + 255)/256, 256>>>((const float4*)Wv,
            (uint2*)wvt_ptr, (uint2*)wvt_ptr + n4, n4);
        n4 = HIDDEN*QDIM/4;
        cvt_bf16_kernel<<<(n4 + 255)/256, 256>>>((const float4*)Wo,
            (uint2*)wot_ptr, (uint2*)wot_ptr + n4, n4);
    }

    lora_qkv_kernel<<<BB*SEQ/4, 256>>>(x, Aq, Ak, Av, t_ptr);

    const size_t TS = (size_t)BB*SEQ*RL;
    const uint32_t* xh = xt_ptr;
    const uint32_t* xl = xt_ptr + (size_t)BB*SEQ*HIDDEN/2;
    gemm_lora_v9<<<dim3(QDIM/BN, SEQ/BM, BB), 128, GEMM_SMEM>>>(
        xh, xl, wqt_ptr, wqt_ptr + (size_t)QDIM*HIDDEN/2,
        t_ptr,        Bq, q_ptr, QDIM, HIDDEN);
    gemm_lora_v9<<<dim3(KVDIM/BN, SEQ/BM, BB), 128, GEMM_SMEM>>>(
        xh, xl, wkt_ptr, wkt_ptr + (size_t)KVDIM*HIDDEN/2,
        t_ptr + TS,   Bk, k_ptr, KVDIM, HIDDEN);
    gemm_lora_v9<<<dim3(KVDIM/BN, SEQ/BM, BB), 128, GEMM_SMEM>>>(
        xh, xl, wvt_ptr, wvt_ptr + (size_t)KVDIM*HIDDEN/2,
        t_ptr + 2*TS, Bv, v_ptr, KVDIM, HIDDEN);

    kprep_kernel<<<dim3(NTILE, NKV, BB), 256>>>();
    vprep_kernel<<<dim3(NTILE, NKV, BB), 256>>>();

    attn_mma_kernel<<<dim3(NTILE, NH, BB), 256, ATTN_SMEM>>>();

    lora_a_kernel<<<BB*SEQ/4, 256>>>(attn_ptr, Ao, t_ptr, QDIM);
    {
        int n4 = BB*SEQ*QDIM/4;
        cvt_bf16_kernel<<<(n4 + 255)/256, 256>>>((const float4*)attn_ptr,
            (uint2*)at_ptr, (uint2*)at_ptr + n4, n4);
    }
    gemm_lora_v9<<<dim3(HIDDEN/BN, SEQ/BM, BB), 128, GEMM_SMEM>>>(
        at_ptr, at_ptr + (size_t)BB*SEQ*QDIM/2,
        wot_ptr, wot_ptr + (size_t)HIDDEN*QDIM/2,
        t_ptr, Bo, out, HIDDEN, QDIM);
}

// round 17
// speedup vs baseline: 1.8254x; 1.8254x over previous
#include <cuda_runtime.h>
#include <math.h>
#include <stdint.h>

#define BB 4
#define SEQ 1024
#define HIDDEN 4096
#define NH 32
#define NKV 8
#define DH 128
#define RL 16
#define QDIM (NH*DH)
#define KVDIM (NKV*DH)
#define NTILE (SEQ/64)

__device__ float g_q[(size_t)BB*SEQ*QDIM];
__device__ float g_k[(size_t)BB*SEQ*KVDIM];
__device__ float g_v[(size_t)BB*SEQ*KVDIM];
__device__ float g_attn[(size_t)BB*SEQ*QDIM];
__device__ float g_t[(size_t)3*BB*SEQ*RL];
__device__ float g_cos[SEQ*(DH/2)];
__device__ float g_sin[SEQ*(DH/2)];
// fp16 packed operands (pair words), half the fp32 footprint
__device__ uint32_t g_xt[(size_t)BB*SEQ*HIDDEN/2];
__device__ uint32_t g_wqt[(size_t)QDIM*HIDDEN/2];
__device__ uint32_t g_wkt[(size_t)KVDIM*HIDDEN/2];
__device__ uint32_t g_wvt[(size_t)KVDIM*HIDDEN/2];
__device__ uint32_t g_wot[(size_t)HIDDEN*QDIM/2];
__device__ uint32_t g_at[(size_t)BB*SEQ*QDIM/2];

#define KTILE_W (2*64*68)
#define VTILE_W (2*128*36)
__device__ uint32_t g_kp[(size_t)BB*NKV*NTILE*KTILE_W];
__device__ uint32_t g_vp[(size_t)BB*NKV*NTILE*VTILE_W];

__device__ __forceinline__ uint32_t pbf2(float lo, float hi) {
    uint32_t r;
    asm("cvt.rn.bf16x2.f32 %0, %1, %2;" : "=r"(r) : "f"(hi), "f"(lo));
    return r;
}
__device__ __forceinline__ uint32_t pf16(float lo, float hi) {
    uint32_t r;
    asm("cvt.rn.f16x2.f32 %0, %1, %2;" : "=r"(r) : "f"(hi), "f"(lo));
    return r;
}
__device__ __forceinline__ float xlo(uint32_t w) { return __uint_as_float(w << 16); }
__device__ __forceinline__ float xhi(uint32_t w) { return __uint_as_float(w & 0xffff0000u); }

#define MMA_BF16(c0,c1,c2,c3,a0,a1,a2,a3,b0,b1)                              \
    asm volatile("mma.sync.aligned.m16n8k16.row.col.f32.bf16.bf16.f32 "      \
        "{%0,%1,%2,%3}, {%4,%5,%6,%7}, {%8,%9}, {%0,%1,%2,%3};"              \
        : "+f"(c0),"+f"(c1),"+f"(c2),"+f"(c3)                                \
        : "r"(a0),"r"(a1),"r"(a2),"r"(a3),"r"(b0),"r"(b1))

#define MMA_F16(c0,c1,c2,c3,a0,a1,a2,a3,b0,b1)                               \
    asm volatile("mma.sync.aligned.m16n8k16.row.col.f32.f16.f16.f32 "        \
        "{%0,%1,%2,%3}, {%4,%5,%6,%7}, {%8,%9}, {%0,%1,%2,%3};"              \
        : "+f"(c0),"+f"(c1),"+f"(c2),"+f"(c3)                                \
        : "r"(a0),"r"(a1),"r"(a2),"r"(a3),"r"(b0),"r"(b1))

__device__ __forceinline__ void cp_async16(void* smem_dst, const void* gsrc) {
    uint32_t d = (uint32_t)__cvta_generic_to_shared(smem_dst);
    asm volatile("cp.async.cg.shared.global [%0], [%1], 16;" :: "r"(d), "l"(gsrc));
}
__device__ __forceinline__ void cp_commit() {
    asm volatile("cp.async.commit_group;");
}

// pack fp32 stream into fp16 pair words
__global__ void cvt_f16_kernel(const float4* __restrict__ in,
                               uint2* __restrict__ out, int n4) {
    int i = blockIdx.x * blockDim.x + threadIdx.x;
    if (i >= n4) return;
    float4 v = in[i];
    out[i] = make_uint2(pf16(v.x, v.y), pf16(v.z, v.w));
}

__global__ void rope_tables_kernel() {
    int idx = blockIdx.x * blockDim.x + threadIdx.x;
    if (idx >= SEQ * (DH/2)) return;
    int s = idx / (DH/2);
    int j = idx % (DH/2);
    float e = -(float)j * (13.287712379549449f / 64.0f);
    float inv = exp2f(e);
    float ang = (float)s * inv;
    g_cos[idx] = cosf(ang);
    g_sin[idx] = sinf(ang);
}

__global__ __launch_bounds__(256) void lora_qkv_kernel(
    const float* __restrict__ x, const float* __restrict__ Aq,
    const float* __restrict__ Ak, const float* __restrict__ Av,
    float* __restrict__ t)
{
    const int g = threadIdx.x >> 6;
    const int j = threadIdx.x & 63;
    const int row = blockIdx.x * 4 + g;
    const int b = row / SEQ;
    const float* xr = x + (size_t)row * HIDDEN;
    const float* Ab0 = Aq + (size_t)b * RL * HIDDEN;
    const float* Ab1 = Ak + (size_t)b * RL * HIDDEN;
    const float* Ab2 = Av + (size_t)b * RL * HIDDEN;

    float acc[3][RL];
#pragma unroll
    for (int p = 0; p < 3; p++)
#pragma unroll
        for (int r = 0; r < RL; r++) acc[p][r] = 0.f;

    for (int k = j * 4; k < HIDDEN; k += 256) {
        float4 xv = *(const float4*)(xr + k);
#pragma unroll
        for (int r = 0; r < RL; r++) {
            float4 a0 = *(const float4*)(Ab0 + (size_t)r * HIDDEN + k);
            float4 a1 = *(const float4*)(Ab1 + (size_t)r * HIDDEN + k);
            float4 a2 = *(const float4*)(Ab2 + (size_t)r * HIDDEN + k);
            acc[0][r] += fmaf(xv.x, a0.x, fmaf(xv.y, a0.y, fmaf(xv.z, a0.z, xv.w * a0.w)));
            acc[1][r] += fmaf(xv.x, a1.x, fmaf(xv.y, a1.y, fmaf(xv.z, a1.z, xv.w * a1.w)));
            acc[2][r] += fmaf(xv.x, a2.x, fmaf(xv.y, a2.y, fmaf(xv.z, a2.z, xv.w * a2.w)));
        }
    }

    __shared__ float red[4][64][17];
#pragma unroll
    for (int p = 0; p < 3; p++) {
        __syncthreads();
#pragma unroll
        for (int r = 0; r < RL; r++) red[g][j][r] = acc[p][r];
        __syncthreads();
        if (j < RL) {
            float s = 0.f;
#pragma unroll 8
            for (int jj = 0; jj < 64; jj++) s += red[g][jj][j];
            t[(size_t)p * BB * SEQ * RL + (size_t)row * RL + j] = s;
        }
    }
}

__global__ __launch_bounds__(256) void lora_a_kernel(
    const float* __restrict__ x, const float* __restrict__ A,
    float* __restrict__ t, int K)
{
    const int g = threadIdx.x >> 6;
    const int j = threadIdx.x & 63;
    const int row = blockIdx.x * 4 + g;
    const int b = row / SEQ;
    const float* xr = x + (size_t)row * K;
    const float* Ab = A + (size_t)b * RL * K;

    float acc[RL];
#pragma unroll
    for (int r = 0; r < RL; r++) acc[r] = 0.f;

    for (int k = j * 4; k < K; k += 256) {
        float4 xv = *(const float4*)(xr + k);
#pragma unroll
        for (int r = 0; r < RL; r++) {
            float4 av = *(const float4*)(Ab + (size_t)r * K + k);
            acc[r] += fmaf(xv.x, av.x, fmaf(xv.y, av.y, fmaf(xv.z, av.z, xv.w * av.w)));
        }
    }

    __shared__ float red[4][64][17];
#pragma unroll
    for (int r = 0; r < RL; r++) red[g][j][r] = acc[r];
    __syncthreads();
    if (j < RL) {
        float s = 0.f;
#pragma unroll 8
        for (int jj = 0; jj < 64; jj++) s += red[g][jj][j];
        t[(size_t)row * RL + j] = s;
    }
}

// ---------------- fp16 MMA GEMM v10: 64x64 warp tile, 128 threads ------------
// smem per stage: A[128][20] + B[128][20] pair words; 2 stages = 40960 B
#define BM 128
#define BN 128
#define BK 32
#define KPB 20
#define STG10 (2*128*KPB)
#define GEMM_SMEM (2*STG10*4)

__global__ __launch_bounds__(128, 2) void gemm_lora_v10(
    const uint32_t* __restrict__ Xh, const uint32_t* __restrict__ Wh,
    const float* __restrict__ T, const float* __restrict__ BL,
    float* __restrict__ C, int N, int K)
{
    extern __shared__ uint32_t sm3[];

    const int b  = blockIdx.z;
    const int n0 = blockIdx.x * BN;
    const int m0 = blockIdx.y * BM;
    const int KP = K >> 1;
    const uint32_t* Xb = Xh + (size_t)b * SEQ * KP;
    const float* Tb = T + (size_t)b * SEQ * RL;
    const float* Ub = BL + (size_t)b * N * RL;
    float* Cb = C + (size_t)b * SEQ * N;

    const int tid  = threadIdx.x;
    const int warp = tid >> 5;
    const int lane = tid & 31;
    const int wm = (warp & 1) * 64;
    const int wn = (warp >> 1) * 64;
    const int gid = lane >> 2;
    const int tig = lane & 3;

    float acc[4][8][4];
#pragma unroll
    for (int mf = 0; mf < 4; mf++)
#pragma unroll
        for (int nf = 0; nf < 8; nf++)
#pragma unroll
            for (int c = 0; c < 4; c++) acc[mf][nf][c] = 0.f;

    const int KT = K / BK;

    {
        uint32_t* As = sm3;
        uint32_t* Bs = sm3 + 128*KPB;
#pragma unroll
        for (int i = 0; i < 4; i++) {
            int idx = tid + i * 128;
            int row = idx >> 2, seg = idx & 3;
            cp_async16(&As[row*KPB + seg*4], Xb + (size_t)(m0 + row) * KP + seg*4);
            cp_async16(&Bs[row*KPB + seg*4], Wh + (size_t)(n0 + row) * KP + seg*4);
        }
        cp_commit();
    }

    for (int kt = 0; kt < KT; kt++) {
        const int s = kt & 1;
        if (kt + 1 < KT) {
            const int sn = s ^ 1;
            const int k0p = (kt + 1) * (BK/2);
            uint32_t* As = sm3 + sn*STG10;
            uint32_t* Bs = As + 128*KPB;
#pragma unroll
            for (int i = 0; i < 4; i++) {
                int idx = tid + i * 128;
                int row = idx >> 2, seg = idx & 3;
                cp_async16(&As[row*KPB + seg*4], Xb + (size_t)(m0 + row) * KP + k0p + seg*4);
                cp_async16(&Bs[row*KPB + seg*4], Wh + (size_t)(n0 + row) * KP + k0p + seg*4);
            }
            cp_commit();
            asm volatile("cp.async.wait_group 1;");
        } else {
            asm volatile("cp.async.wait_group 0;");
        }
        __syncthreads();

        const uint32_t* As = sm3 + s*STG10;
        const uint32_t* Bs = As + 128*KPB;
#pragma unroll
        for (int ks = 0; ks < 2; ks++) {
            const int kb = ks * 8;
            uint32_t a[4][4];
#pragma unroll
            for (int mf = 0; mf < 4; mf++) {
                int r0 = (wm + mf*16 + gid) * KPB + kb;
                int r1 = (wm + mf*16 + 8 + gid) * KPB + kb;
                a[mf][0] = As[r0 + tig];     a[mf][1] = As[r1 + tig];
                a[mf][2] = As[r0 + tig + 4]; a[mf][3] = As[r1 + tig + 4];
            }
#pragma unroll
            for (int nf = 0; nf < 8; nf++) {
                int nr = (wn + nf*8 + gid) * KPB + kb;
                uint32_t b0 = Bs[nr + tig], b1 = Bs[nr + tig + 4];
#pragma unroll
                for (int mf = 0; mf < 4; mf++)
                    MMA_F16(acc[mf][nf][0], acc[mf][nf][1], acc[mf][nf][2], acc[mf][nf][3],
                            a[mf][0], a[mf][1], a[mf][2], a[mf][3], b0, b1);
            }
        }
        __syncthreads();
    }

    float* Ts = (float*)sm3;
    float* Us = (float*)(sm3 + 128 * RL);
#pragma unroll
    for (int i = 0; i < 4; i++) {
        int f4 = tid + i * 128;
        int row = f4 >> 2;
        int c4 = (f4 & 3) * 4;
        *(float4*)&Ts[row * RL + c4] = *(const float4*)&Tb[(size_t)(m0 + row) * RL + c4];
        *(float4*)&Us[row * RL + c4] = *(const float4*)&Ub[(size_t)(n0 + row) * RL + c4];
    }
    __syncthreads();

#pragma unroll
    for (int mf = 0; mf < 4; mf++) {
#pragma unroll
        for (int rr = 0; rr < 2; rr++) {
            int m_local = wm + mf * 16 + rr * 8 + gid;
            float tv[RL];
#pragma unroll
            for (int r = 0; r < RL; r++) tv[r] = Ts[m_local * RL + r];
            size_t crow = (size_t)(m0 + m_local) * N + n0;
#pragma unroll
            for (int nf = 0; nf < 8; nf++) {
                int n_local = wn + nf * 8 + 2 * tig;
                float s0 = acc[mf][nf][rr * 2 + 0];
                float s1 = acc[mf][nf][rr * 2 + 1];
#pragma unroll
                for (int r = 0; r < RL; r++) {
                    s0 = fmaf(tv[r], Us[n_local * RL + r], s0);
                    s1 = fmaf(tv[r], Us[(n_local + 1) * RL + r], s1);
                }
                *(float2*)&Cb[crow + n_local] = make_float2(s0, s1);
            }
        }
    }
}

__global__ __launch_bounds__(256) void kprep_kernel() {
    const int jt = blockIdx.x, hk = blockIdx.y, b = blockIdx.z;
    const int tid = threadIdx.x;
    const int r = tid >> 2;
    const int pb = (tid & 3) * 16;
    const int s = jt * 64 + r;
    const float* src = g_k + (((size_t)(b * SEQ + s)) * NKV + hk) * DH;
    size_t tile = ((size_t)(b * NKV + hk) * NTILE + jt);
    uint32_t* dhi = g_kp + tile * KTILE_W + (size_t)r * 68;
    uint32_t* dlo = dhi + 64 * 68;

#pragma unroll
    for (int u4 = 0; u4 < 4; u4++) {
        float4 xa = *(const float4*)(src + pb + u4 * 4);
        float4 xb = *(const float4*)(src + pb + 64 + u4 * 4);
        float4 cc = *(const float4*)(g_cos + s * 64 + pb + u4 * 4);
        float4 ss = *(const float4*)(g_sin + s * 64 + pb + u4 * 4);
        float x1[4] = {xa.x, xa.y, xa.z, xa.w};
        float x2[4] = {xb.x, xb.y, xb.z, xb.w};
        float cv[4] = {cc.x, cc.y, cc.z, cc.w};
        float sv[4] = {ss.x, ss.y, ss.z, ss.w};
        float y1[4], y2[4];
#pragma unroll
        for (int e = 0; e < 4; e++) {
            y1[e] = fmaf(x1[e], cv[e], -x2[e] * sv[e]);
            y2[e] = fmaf(x2[e], cv[e],  x1[e] * sv[e]);
        }
        int p1 = (pb + u4 * 4) >> 1;
#pragma unroll
        for (int pp = 0; pp < 2; pp++) {
            float a0 = y1[pp*2], a1 = y1[pp*2+1];
            uint32_t hw = pbf2(a0, a1);
            uint32_t lw = pbf2(a0 - xlo(hw), a1 - xhi(hw));
            dhi[p1 + pp] = hw;
            dlo[p1 + pp] = lw;
            float b0 = y2[pp*2], b1 = y2[pp*2+1];
            uint32_t hw2 = pbf2(b0, b1);
            uint32_t lw2 = pbf2(b0 - xlo(hw2), b1 - xhi(hw2));
            dhi[p1 + 32 + pp] = hw2;
            dlo[p1 + 32 + pp] = lw2;
        }
    }
}

__global__ __launch_bounds__(256) void vprep_kernel() {
    const int jt = blockIdx.x, hk = blockIdx.y, b = blockIdx.z;
    const int tid = threadIdx.x;
    const int jp = tid & 31;
    const int dblk = tid >> 5;
    const float* s0 = g_v + (((size_t)(b * SEQ + jt * 64 + 2*jp))   * NKV + hk) * DH + dblk * 16;
    const float* s1 = g_v + (((size_t)(b * SEQ + jt * 64 + 2*jp+1)) * NKV + hk) * DH + dblk * 16;
    size_t tile = ((size_t)(b * NKV + hk) * NTILE + jt);
    uint32_t* dhi = g_vp + tile * VTILE_W;
    uint32_t* dlo = dhi + 128 * 36;

#pragma unroll
    for (int u = 0; u < 4; u++) {
        float4 va = *(const float4*)(s0 + u * 4);
        float4 vb = *(const float4*)(s1 + u * 4);
        float a[4] = {va.x, va.y, va.z, va.w};
        float bb[4] = {vb.x, vb.y, vb.z, vb.w};
#pragma unroll
        for (int e = 0; e < 4; e++) {
            int d = dblk * 16 + u * 4 + e;
            uint32_t hw = pbf2(a[e], bb[e]);
            uint32_t lw = pbf2(a[e] - xlo(hw), bb[e] - xhi(hw));
            dhi[d * 36 + jp] = hw;
            dlo[d * 36 + jp] = lw;
        }
    }
}

#define ATTN_SMEM 214784
#define QPS 68
#define VPS 36
#define PSS 68
#define STG_W 17920

__global__ __launch_bounds__(256, 1) void attn_mma_kernel() {
    extern __shared__ char smraw[];
    uint32_t* smw = (uint32_t*)smraw;
    uint32_t* Qhi = smw;
    uint32_t* Qlo = smw + 4352;
    float*    Psf = (float*)(smw + 44544);
    uint32_t* Phi = smw + 48896;
    uint32_t* Plo = smw + 51200;
    float* mrow = (float*)(smw + 53504);
    float* lrow = mrow + 64;
    float* arow = mrow + 128;

    const int qt = (NTILE - 1) - blockIdx.x;
    const int h  = blockIdx.y;
    const int b  = blockIdx.z;
    const int hk = h >> 2;
    const int tid  = threadIdx.x;
    const int warp = tid >> 5;
    const int lane = tid & 31;
    const int gid = lane >> 2;
    const int tig = lane & 3;
    const int wm  = (warp & 3) * 16;
    const int wn  = (warp >> 2) * 32;
    const int wdn = (warp >> 2) * 64;

    const size_t tbase = (size_t)(b * NKV + hk) * NTILE;
    const float scale = 0.08838834764831845f;

    {
        const char* gk = (const char*)(g_kp + (tbase + 0) * KTILE_W);
        char* sk = smraw + 8704 * 4;
#pragma unroll
        for (int i = 0; i < 9; i++) {
            int idx = tid + i * 256;
            if (idx < 2176) cp_async16(sk + idx * 16, gk + idx * 16);
        }
        const char* gv = (const char*)(g_vp + (tbase + 0) * VTILE_W);
        char* sv = sk + 34816;
#pragma unroll
        for (int i = 0; i < 9; i++) {
            int idx = tid + i * 256;
            cp_async16(sv + idx * 16, gv + idx * 16);
        }
        cp_commit();
    }

    {
        int r = tid >> 2;
        int q4 = tid & 3;
        int sg = qt * 64 + r;
        const float* src = g_q + (((size_t)(b * SEQ + sg)) * NH + h) * DH;
        const float* cb = g_cos + sg * 64 + q4 * 16;
        const float* sb = g_sin + sg * 64 + q4 * 16;
        int pA = q4 * 8;
#pragma unroll
        for (int u = 0; u < 4; u++) {
            float4 xa = *(const float4*)(src + q4 * 16 + u * 4);
            float4 xb = *(const float4*)(src + q4 * 16 + 64 + u * 4);
            float4 cc = *(const float4*)(cb + u * 4);
            float4 ss = *(const float4*)(sb + u * 4);
            float x1[4] = {xa.x, xa.y, xa.z, xa.w};
            float x2[4] = {xb.x, xb.y, xb.z, xb.w};
            float cv[4] = {cc.x, cc.y, cc.z, cc.w};
            float sv[4] = {ss.x, ss.y, ss.z, ss.w};
            float y1[4], y2[4];
#pragma unroll
            for (int e = 0; e < 4; e++) {
                y1[e] = fmaf(x1[e], cv[e], -x2[e] * sv[e]) * scale;
                y2[e] = fmaf(x2[e], cv[e],  x1[e] * sv[e]) * scale;
            }
            int cbase = r * QPS + pA + u * 2;
#pragma unroll
            for (int pp = 0; pp < 2; pp++) {
                uint32_t hw = pbf2(y1[pp*2], y1[pp*2+1]);
                uint32_t lw = pbf2(y1[pp*2] - xlo(hw), y1[pp*2+1] - xhi(hw));
                Qhi[cbase + pp] = hw;
                Qlo[cbase + pp] = lw;
                uint32_t hw2 = pbf2(y2[pp*2], y2[pp*2+1]);
                uint32_t lw2 = pbf2(y2[pp*2] - xlo(hw2), y2[pp*2+1] - xhi(hw2));
                Qhi[cbase + 32 + pp] = hw2;
                Qlo[cbase + 32 + pp] = lw2;
            }
        }
    }
    if (tid < 64) { mrow[tid] = -1e30f; lrow[tid] = 0.f; }
    __syncthreads();

    uint32_t ah[8][4];
#pragma unroll
    for (int ks = 0; ks < 8; ks++) {
        int kb = ks * 8;
        ah[ks][0] = Qhi[(wm + gid)     * QPS + kb + tig];
        ah[ks][1] = Qhi[(wm + gid + 8) * QPS + kb + tig];
        ah[ks][2] = Qhi[(wm + gid)     * QPS + kb + tig + 4];
        ah[ks][3] = Qhi[(wm + gid + 8) * QPS + kb + tig + 4];
    }

    float o[8][4];
#pragma unroll
    for (int nf = 0; nf < 8; nf++)
#pragma unroll
        for (int c = 0; c < 4; c++) o[nf][c] = 0.f;

    for (int jt = 0; jt <= qt; jt++) {
        const int st = jt & 1;
        uint32_t* Khi = smw + 8704 + st * STG_W;
        uint32_t* Klo = Khi + 4352;
        uint32_t* Vhi = Khi + 8704;
        uint32_t* Vlo = Khi + 13312;

        asm volatile("cp.async.wait_group 0;");
        __syncthreads();

        if (jt < qt) {
            const int sn = st ^ 1;
            const char* gk = (const char*)(g_kp + (tbase + jt + 1) * KTILE_W);
            char* sk = smraw + (8704 + sn * STG_W) * 4;
#pragma unroll
            for (int i = 0; i < 9; i++) {
                int idx = tid + i * 256;
                if (idx < 2176) cp_async16(sk + idx * 16, gk + idx * 16);
            }
            const char* gv = (const char*)(g_vp + (tbase + jt + 1) * VTILE_W);
            char* sv = sk + 34816;
#pragma unroll
            for (int i = 0; i < 9; i++) {
                int idx = tid + i * 256;
                cp_async16(sv + idx * 16, gv + idx * 16);
            }
            cp_commit();
        }

        float s[4][4];
#pragma unroll
        for (int nf = 0; nf < 4; nf++)
#pragma unroll
            for (int c = 0; c < 4; c++) s[nf][c] = 0.f;

#pragma unroll
        for (int ks = 0; ks < 8; ks++) {
            int kb = ks * 8;
            uint32_t ql0 = Qlo[(wm + gid)     * QPS + kb + tig];
            uint32_t ql1 = Qlo[(wm + gid + 8) * QPS + kb + tig];
            uint32_t ql2 = Qlo[(wm + gid)     * QPS + kb + tig + 4];
            uint32_t ql3 = Qlo[(wm + gid + 8) * QPS + kb + tig + 4];
#pragma unroll
            for (int nf = 0; nf < 4; nf++) {
                int nr = (wn + nf * 8 + gid) * QPS + kb;
                uint32_t bh0 = Khi[nr + tig];
                uint32_t bh1 = Khi[nr + tig + 4];
                uint32_t bl0 = Klo[nr + tig];
                uint32_t bl1 = Klo[nr + tig + 4];
                MMA_BF16(s[nf][0], s[nf][1], s[nf][2], s[nf][3],
                         ah[ks][0], ah[ks][1], ah[ks][2], ah[ks][3], bh0, bh1);
                MMA_BF16(s[nf][0], s[nf][1], s[nf][2], s[nf][3],
                         ql0, ql1, ql2, ql3, bh0, bh1);
                MMA_BF16(s[nf][0], s[nf][1], s[nf][2], s[nf][3],
                         ah[ks][0], ah[ks][1], ah[ks][2], ah[ks][3], bl0, bl1);
            }
        }

        {
            int row0 = wm + gid, row1 = row0 + 8;
            int rg0 = qt * 64 + row0, rg1 = qt * 64 + row1;
#pragma unroll
            for (int nf = 0; nf < 4; nf++) {
                int cc = wn + nf * 8 + 2 * tig;
                int cg = jt * 64 + cc;
                float2 w0, w1;
                w0.x = (cg     <= rg0) ? s[nf][0] : -1e30f;
                w0.y = (cg + 1 <= rg0) ? s[nf][1] : -1e30f;
                w1.x = (cg     <= rg1) ? s[nf][2] : -1e30f;
                w1.y = (cg + 1 <= rg1) ? s[nf][3] : -1e30f;
                *(float2*)(Psf + row0 * PSS + cc) = w0;
                *(float2*)(Psf + row1 * PSS + cc) = w1;
            }
        }
        __syncthreads();

        {
            int sr = tid >> 2;
            int t4 = tid & 3;
            float* prow = Psf + sr * PSS + t4 * 16;
            float pv[16];
            float mx = -1e30f;
#pragma unroll
            for (int i = 0; i < 16; i++) { pv[i] = prow[i]; mx = fmaxf(mx, pv[i]); }
            mx = fmaxf(mx, __shfl_xor_sync(0xffffffffu, mx, 1));
            mx = fmaxf(mx, __shfl_xor_sync(0xffffffffu, mx, 2));
            float mo = mrow[sr];
            mx = fmaxf(mx, mo);
            float sum = 0.f;
            uint32_t* ph = Phi + sr * VPS + t4 * 8;
            uint32_t* pl = Plo + sr * VPS + t4 * 8;
#pragma unroll
            for (int i = 0; i < 8; i++) {
                float e0 = __expf(pv[2*i]   - mx);
                float e1 = __expf(pv[2*i+1] - mx);
                sum += e0 + e1;
                uint32_t hw = pbf2(e0, e1);
                uint32_t lw = pbf2(e0 - xlo(hw), e1 - xhi(hw));
                ph[i] = hw;
                pl[i] = lw;
            }
            sum += __shfl_xor_sync(0xffffffffu, sum, 1);
            sum += __shfl_xor_sync(0xffffffffu, sum, 2);
            if (t4 == 0) {
                float alp = __expf(mo - mx);
                lrow[sr] = lrow[sr] * alp + sum;
                mrow[sr] = mx;
                arow[sr] = alp;
            }
        }
        __syncthreads();

        {
            float a0 = arow[wm + gid];
            float a1 = arow[wm + gid + 8];
#pragma unroll
            for (int nf = 0; nf < 8; nf++) {
                o[nf][0] *= a0; o[nf][1] *= a0;
                o[nf][2] *= a1; o[nf][3] *= a1;
            }
        }

#pragma unroll
        for (int ks = 0; ks < 4; ks++) {
            int kb = ks * 8;
            uint32_t ph0 = Phi[(wm + gid)     * VPS + kb + tig];
            uint32_t ph1 = Phi[(wm + gid + 8) * VPS + kb + tig];
            uint32_t ph2 = Phi[(wm + gid)     * VPS + kb + tig + 4];
            uint32_t ph3 = Phi[(wm + gid + 8) * VPS + kb + tig + 4];
            uint32_t pl0 = Plo[(wm + gid)     * VPS + kb + tig];
            uint32_t pl1 = Plo[(wm + gid + 8) * VPS + kb + tig];
            uint32_t pl2 = Plo[(wm + gid)     * VPS + kb + tig + 4];
            uint32_t pl3 = Plo[(wm + gid + 8) * VPS + kb + tig + 4];
#pragma unroll
            for (int nf = 0; nf < 8; nf++) {
                int dv = (wdn + nf * 8 + gid) * VPS + kb;
                uint32_t vh0 = Vhi[dv + tig], vh1 = Vhi[dv + tig + 4];
                uint32_t vl0 = Vlo[dv + tig], vl1 = Vlo[dv + tig + 4];
                MMA_BF16(o[nf][0], o[nf][1], o[nf][2], o[nf][3],
                         ph0, ph1, ph2, ph3, vh0, vh1);
                MMA_BF16(o[nf][0], o[nf][1], o[nf][2], o[nf][3],
                         pl0, pl1, pl2, pl3, vh0, vh1);
                MMA_BF16(o[nf][0], o[nf][1], o[nf][2], o[nf][3],
                         ph0, ph1, ph2, ph3, vl0, vl1);
            }
        }
    }

    {
        float li0 = 1.f / lrow[wm + gid];
        float li1 = 1.f / lrow[wm + gid + 8];
        size_t base0 = (((size_t)(b * SEQ + qt * 64 + wm + gid))     * NH + h) * DH;
        size_t base1 = (((size_t)(b * SEQ + qt * 64 + wm + gid + 8)) * NH + h) * DH;
#pragma unroll
        for (int nf = 0; nf < 8; nf++) {
            int cc = wdn + nf * 8 + 2 * tig;
            *(float2*)(g_attn + base0 + cc) = make_float2(o[nf][0] * li0, o[nf][1] * li0);
            *(float2*)(g_attn + base1 + cc) = make_float2(o[nf][2] * li1, o[nf][3] * li1);
        }
    }
}

extern "C" void kernel_launch(void* const* d_in, const int* in_sizes, int n_in,
                              void* d_out, int out_size) {
    const float* x  = (const float*)d_in[0];
    const float* Wq = (const float*)d_in[1];
    const float* Wk = (const float*)d_in[2];
    const float* Wv = (const float*)d_in[3];
    const float* Wo = (const float*)d_in[4];
    const float* Aq = (const float*)d_in[5];
    const float* Bq = (const float*)d_in[6];
    const float* Ak = (const float*)d_in[7];
    const float* Bk = (const float*)d_in[8];
    const float* Av = (const float*)d_in[9];
    const float* Bv = (const float*)d_in[10];
    const float* Ao = (const float*)d_in[11];
    const float* Bo = (const float*)d_in[12];
    float* out = (float*)d_out;

    float *q_ptr, *k_ptr, *v_ptr, *attn_ptr, *t_ptr;
    uint32_t *xt_ptr, *wqt_ptr, *wkt_ptr, *wvt_ptr, *wot_ptr, *at_ptr;
    cudaGetSymbolAddress((void**)&q_ptr, g_q);
    cudaGetSymbolAddress((void**)&k_ptr, g_k);
    cudaGetSymbolAddress((void**)&v_ptr, g_v);
    cudaGetSymbolAddress((void**)&attn_ptr, g_attn);
    cudaGetSymbolAddress((void**)&t_ptr, g_t);
    cudaGetSymbolAddress((void**)&xt_ptr, g_xt);
    cudaGetSymbolAddress((void**)&wqt_ptr, g_wqt);
    cudaGetSymbolAddress((void**)&wkt_ptr, g_wkt);
    cudaGetSymbolAddress((void**)&wvt_ptr, g_wvt);
    cudaGetSymbolAddress((void**)&wot_ptr, g_wot);
    cudaGetSymbolAddress((void**)&at_ptr, g_at);

    cudaFuncSetAttribute(attn_mma_kernel,
                         cudaFuncAttributeMaxDynamicSharedMemorySize, ATTN_SMEM);
    cudaFuncSetAttribute(gemm_lora_v10,
                         cudaFuncAttributeMaxDynamicSharedMemorySize, GEMM_SMEM);

    rope_tables_kernel<<<(SEQ*(DH/2) + 255)/256, 256>>>();

    // fp16 pack of GEMM operands
    {
        int n4;
        n4 = BB*SEQ*HIDDEN/4;
        cvt_f16_kernel<<<(n4 + 255)/256, 256>>>((const float4*)x, (uint2*)xt_ptr, n4);
        n4 = QDIM*HIDDEN/4;
        cvt_f16_kernel<<<(n4 + 255)/256, 256>>>((const float4*)Wq, (uint2*)wqt_ptr, n4);
        n4 = KVDIM*HIDDEN/4;
        cvt_f16_kernel<<<(n4 + 255)/256, 256>>>((const float4*)Wk, (uint2*)wkt_ptr, n4);
        cvt_f16_kernel<<<(n4 + 255)/256, 256>>>((const float4*)Wv, (uint2*)wvt_ptr, n4);
        n4 = HIDDEN*QDIM/4;
        cvt_f16_kernel<<<(n4 + 255)/256, 256>>>((const float4*)Wo, (uint2*)wot_ptr, n4);
    }

    lora_qkv_kernel<<<BB*SEQ/4, 256>>>(x, Aq, Ak, Av, t_ptr);

    const size_t TS = (size_t)BB*SEQ*RL;
    gemm_lora_v10<<<dim3(QDIM/BN, SEQ/BM, BB), 128, GEMM_SMEM>>>(
        xt_ptr, wqt_ptr, t_ptr,        Bq, q_ptr, QDIM, HIDDEN);
    gemm_lora_v10<<<dim3(KVDIM/BN, SEQ/BM, BB), 128, GEMM_SMEM>>>(
        xt_ptr, wkt_ptr, t_ptr + TS,   Bk, k_ptr, KVDIM, HIDDEN);
    gemm_lora_v10<<<dim3(KVDIM/BN, SEQ/BM, BB), 128, GEMM_SMEM>>>(
        xt_ptr, wvt_ptr, t_ptr + 2*TS, Bv, v_ptr, KVDIM, HIDDEN);

    kprep_kernel<<<dim3(NTILE, NKV, BB), 256>>>();
    vprep_kernel<<<dim3(NTILE, NKV, BB), 256>>>();

    attn_mma_kernel<<<dim3(NTILE, NH, BB), 256, ATTN_SMEM>>>();

    lora_a_kernel<<<BB*SEQ/4, 256>>>(attn_ptr, Ao, t_ptr, QDIM);
    {
        int n4 = BB*SEQ*QDIM/4;
        cvt_f16_kernel<<<(n4 + 255)/256, 256>>>((const float4*)attn_ptr, (uint2*)at_ptr, n4);
    }
    gemm_lora_v10<<<dim3(HIDDEN/BN, SEQ/BM, BB), 128, GEMM_SMEM>>>(
        at_ptr, wot_ptr, t_ptr, Bo, out, HIDDEN, QDIM);
}